// round 3
// baseline (speedup 1.0000x reference)
#include <cuda_runtime.h>
#include <math.h>

#define N_TOK   8192
#define DM      256
#define NE      16
#define NVIEW   3
#define TOPK    4
#define HID     1024

#define TM      64      // tokens per FFN tile
#define XSP     260     // Xs row stride (floats)
#define HCP     68      // Hc row stride (floats)

// ---------------- device scratch (no allocations allowed) ----------------
__device__ int   g_cnt [NVIEW * NE];
__device__ int   g_tok [NVIEW * NE * N_TOK];
__device__ float g_gate[NVIEW * NE * N_TOK];

// ---------------- helpers ----------------
__device__ __forceinline__ float d4(float4 a, float4 b) {
    return a.x * b.x + a.y * b.y + a.z * b.z + a.w * b.w;
}

__device__ __forceinline__ float wredsum(float x) {
#pragma unroll
    for (int o = 16; o > 0; o >>= 1) x += __shfl_xor_sync(0xffffffffu, x, o);
    return x;
}

__device__ __forceinline__ float gelu_exact(float x) {
    return 0.5f * x * (1.0f + erff(x * 0.70710678118654752440f));
}

// ---------------- kernel 0: zero routing counters ----------------
__global__ void zero_cnt_kernel() {
    if (threadIdx.x < NVIEW * NE) g_cnt[threadIdx.x] = 0;
}

// ---------------- kernel 1: router (one warp per token-view) ----------------
// Reproduce the reference's fp32 rounding sequence exactly:
//   dk = v.k ; dr = v.rw ; kk = |k|^2 ; vv = |v|^2   (separate fp32 reductions)
//   sq = (vv + kk) - 2*dk        (each op fp32-rounded; *2 exact)
//   logit = (-sq) + dr           (fp32-rounded, carries the -|v|^2 offset
//                                 => same ~3e-5 quantization grid as XLA)
__global__ void router_kernel(const float* __restrict__ v0,
                              const float* __restrict__ v1,
                              const float* __restrict__ v2,
                              const float* __restrict__ rw,
                              const float* __restrict__ keys) {
    int vi   = blockIdx.y;
    int warp = threadIdx.x >> 5;
    int lane = threadIdx.x & 31;
    int tok  = blockIdx.x * 8 + warp;
    if (tok >= N_TOK) return;

    const float* vbase = (vi == 0) ? v0 : ((vi == 1) ? v1 : v2);
    const float* v = vbase + tok * DM;

    float4 a = ((const float4*)v)[lane];
    float4 b = ((const float4*)v)[lane + 32];

    float vv = wredsum(d4(a, a) + d4(b, b));

    const float* rwv = rw + (size_t)vi * NE * DM;
    float lg[NE];
#pragma unroll
    for (int e = 0; e < NE; e++) {
        const float4* kp = (const float4*)(keys + e * DM);
        const float4* rp = (const float4*)(rwv + e * DM);
        float4 k1 = kp[lane], k2 = kp[lane + 32];
        float4 r1 = rp[lane], r2 = rp[lane + 32];
        float dk = wredsum(d4(a, k1) + d4(b, k2));   // v . k_e
        float dr = wredsum(d4(a, r1) + d4(b, r2));   // v . rw_e
        float kk = wredsum(d4(k1, k1) + d4(k2, k2)); // |k_e|^2
        float sq = (vv + kk) - 2.0f * dk;
        lg[e] = (-sq) + dr;
    }

    if (lane == 0) {
        unsigned chosen = 0;
        float tv[TOPK];
        int   ti[TOPK];
#pragma unroll
        for (int k = 0; k < TOPK; k++) {
            float m = -1e30f; int mi = 0;
#pragma unroll
            for (int e = 0; e < NE; e++) {
                if (!((chosen >> e) & 1u) && lg[e] > m) { m = lg[e]; mi = e; }
            }
            tv[k] = m; ti[k] = mi; chosen |= (1u << mi);
        }
        float s = 0.f;
        float ex[TOPK];
#pragma unroll
        for (int k = 0; k < TOPK; k++) { ex[k] = expf(tv[k] - tv[0]); s += ex[k]; }
        float inv = 1.0f / s;
#pragma unroll
        for (int k = 0; k < TOPK; k++) {
            int ge  = vi * NE + ti[k];
            int pos = atomicAdd(&g_cnt[ge], 1);
            g_tok [ge * N_TOK + pos] = tok;
            g_gate[ge * N_TOK + pos] = ex[k] * inv;
        }
    }
}

// ---------------- kernel 2: grouped FFN (exact fp32) ----------------
// grid (128, NE, NVIEW), 256 threads. Tile = up to 64 gathered tokens.
extern "C" __global__ void __launch_bounds__(256, 1)
ffn_kernel(const float* __restrict__ v0, const float* __restrict__ v1,
           const float* __restrict__ v2,
           const float* __restrict__ W1, const float* __restrict__ b1,
           const float* __restrict__ W2, const float* __restrict__ b2,
           float* __restrict__ out) {
    extern __shared__ float smem[];
    int vi = blockIdx.z, e = blockIdx.y;
    int g = vi * NE + e;
    int cnt = g_cnt[g];
    int t0 = blockIdx.x * TM;
    if (t0 >= cnt) return;
    int rows = min(TM, cnt - t0);

    float* Xs  = smem;                    // [64][XSP]
    float* W1s = Xs + TM * XSP;           // [64][64]
    float* W2c = W1s + 64 * 64;           // [64][256]
    float* Hc  = W2c + 64 * DM;           // [64][HCP]
    int*   s_tok  = (int*)(Hc + TM * HCP);
    float* s_gate = (float*)(s_tok + TM);

    int tid = threadIdx.x;
    if (tid < TM) {
        int idx = t0 + tid;
        if (idx < cnt) {
            s_tok [tid] = g_tok [g * N_TOK + idx];
            s_gate[tid] = g_gate[g * N_TOK + idx];
        } else {
            s_tok[tid] = 0; s_gate[tid] = 0.0f;
        }
    }
    __syncthreads();

    const float* V = (vi == 0) ? v0 : ((vi == 1) ? v1 : v2);

    // gather X tile (64 rows x 256 floats)
    for (int idx = tid; idx < TM * 64; idx += 256) {
        int r = idx >> 6, c4 = idx & 63;
        float4 val = make_float4(0.f, 0.f, 0.f, 0.f);
        if (r < rows) val = ((const float4*)(V + (size_t)s_tok[r] * DM))[c4];
        *(float4*)&Xs[r * XSP + c4 * 4] = val;
    }

    int ty = tid >> 4, tx = tid & 15;   // 16x16 thread grid
    float acc[4][16];
#pragma unroll
    for (int i = 0; i < 4; i++)
#pragma unroll
        for (int c = 0; c < 16; c++) acc[i][c] = 0.0f;

    const float* W1e = W1 + (size_t)e * DM * HID;
    const float* W2e = W2 + (size_t)e * HID * DM;

    for (int jc = 0; jc < 16; jc++) {
        int j0 = jc * 64;
        __syncthreads();   // previous GEMM2 reads of W2c/Hc done

        // load W2 chunk [64][256]
        for (int idx = tid; idx < 64 * 64; idx += 256) {
            int j = idx >> 6, c4 = idx & 63;
            ((float4*)W2c)[idx] = ((const float4*)(W2e + (size_t)(j0 + j) * DM))[c4];
        }

        float4 hacc[4];
#pragma unroll
        for (int i = 0; i < 4; i++) hacc[i] = make_float4(0.f, 0.f, 0.f, 0.f);

        // GEMM1: Hc[64,64] = X[64,256] * W1[:, j0:j0+64]
        for (int dsl = 0; dsl < 4; dsl++) {
            __syncthreads();
            for (int idx = tid; idx < 64 * 16; idx += 256) {
                int d = idx >> 4, c4 = idx & 15;
                ((float4*)W1s)[idx] =
                    ((const float4*)(W1e + (size_t)(dsl * 64 + d) * HID + j0))[c4];
            }
            __syncthreads();
#pragma unroll
            for (int dq = 0; dq < 16; dq++) {
                float4 w[4];
#pragma unroll
                for (int t = 0; t < 4; t++)
                    w[t] = ((const float4*)W1s)[(dq * 4 + t) * 16 + tx];
#pragma unroll
                for (int i = 0; i < 4; i++) {
                    float4 xv = *(const float4*)&Xs[(ty * 4 + i) * XSP + dsl * 64 + dq * 4];
                    hacc[i].x += xv.x * w[0].x + xv.y * w[1].x + xv.z * w[2].x + xv.w * w[3].x;
                    hacc[i].y += xv.x * w[0].y + xv.y * w[1].y + xv.z * w[2].y + xv.w * w[3].y;
                    hacc[i].z += xv.x * w[0].z + xv.y * w[1].z + xv.z * w[2].z + xv.w * w[3].z;
                    hacc[i].w += xv.x * w[0].w + xv.y * w[1].w + xv.z * w[2].w + xv.w * w[3].w;
                }
            }
        }

        // bias + exact GELU, store Hc
        {
            const float4 bb = *(const float4*)&b1[(size_t)e * HID + j0 + tx * 4];
#pragma unroll
            for (int i = 0; i < 4; i++) {
                float4 hb;
                hb.x = gelu_exact(hacc[i].x + bb.x);
                hb.y = gelu_exact(hacc[i].y + bb.y);
                hb.z = gelu_exact(hacc[i].z + bb.z);
                hb.w = gelu_exact(hacc[i].w + bb.w);
                *(float4*)&Hc[(ty * 4 + i) * HCP + tx * 4] = hb;
            }
        }
        __syncthreads();

        // GEMM2: acc[64,256] += Hc[64,64] * W2c[64,256]
#pragma unroll 2
        for (int j = 0; j < 64; j++) {
            float hr[4];
#pragma unroll
            for (int i = 0; i < 4; i++) hr[i] = Hc[(ty * 4 + i) * HCP + j];
            float4 w4[4];
#pragma unroll
            for (int q = 0; q < 4; q++) w4[q] = ((const float4*)W2c)[j * 64 + tx * 4 + q];
#pragma unroll
            for (int i = 0; i < 4; i++) {
#pragma unroll
                for (int q = 0; q < 4; q++) {
                    acc[i][q * 4 + 0] += hr[i] * w4[q].x;
                    acc[i][q * 4 + 1] += hr[i] * w4[q].y;
                    acc[i][q * 4 + 2] += hr[i] * w4[q].z;
                    acc[i][q * 4 + 3] += hr[i] * w4[q].w;
                }
            }
        }
    }

    // epilogue: out[tok, :] += gate * (acc + b2[e])
    float bb2[16];
#pragma unroll
    for (int q = 0; q < 4; q++) {
        float4 t = *(const float4*)&b2[(size_t)e * DM + tx * 16 + q * 4];
        bb2[q * 4 + 0] = t.x; bb2[q * 4 + 1] = t.y;
        bb2[q * 4 + 2] = t.z; bb2[q * 4 + 3] = t.w;
    }
#pragma unroll
    for (int i = 0; i < 4; i++) {
        int r = ty * 4 + i;
        if (r < rows) {
            float gte = s_gate[r];
            float* ob = out + (size_t)s_tok[r] * DM + tx * 16;
#pragma unroll
            for (int c = 0; c < 16; c++)
                atomicAdd(&ob[c], gte * (acc[i][c] + bb2[c]));
        }
    }
}

// ---------------- launch ----------------
extern "C" void kernel_launch(void* const* d_in, const int* in_sizes, int n_in,
                              void* d_out, int out_size) {
    const float* v0   = (const float*)d_in[0];
    const float* v1   = (const float*)d_in[1];
    const float* v2   = (const float*)d_in[2];
    const float* rw   = (const float*)d_in[3];
    const float* keys = (const float*)d_in[4];
    const float* W1   = (const float*)d_in[5];
    const float* b1   = (const float*)d_in[6];
    const float* W2   = (const float*)d_in[7];
    const float* b2   = (const float*)d_in[8];
    float* out = (float*)d_out;

    static const size_t SMEM_BYTES =
        (TM * XSP + 64 * 64 + 64 * DM + TM * HCP) * sizeof(float)
        + TM * (sizeof(int) + sizeof(float));
    cudaFuncSetAttribute(ffn_kernel, cudaFuncAttributeMaxDynamicSharedMemorySize,
                         (int)SMEM_BYTES);

    cudaMemsetAsync(d_out, 0, (size_t)out_size * sizeof(float), 0);
    zero_cnt_kernel<<<1, 64, 0, 0>>>();

    dim3 rgrid(N_TOK / 8, NVIEW, 1);
    router_kernel<<<rgrid, 256, 0, 0>>>(v0, v1, v2, rw, keys);

    dim3 fgrid(N_TOK / TM, NE, NVIEW);   // 128 x 16 x 3, most blocks exit early
    ffn_kernel<<<fgrid, 256, SMEM_BYTES, 0>>>(v0, v1, v2, W1, b1, W2, b2, out);
}

// round 5
// speedup vs baseline: 6.0471x; 6.0471x over previous
#include <cuda_runtime.h>
#include <math.h>
#include <cstdint>

#define N_TOK   8192
#define DM      256
#define NE      16
#define NVIEW   3
#define TOPK    4
#define HID     1024
#define TM      64

// ---- ffn smem layout (float indices) ----
#define XP_F    0           // Xperm: 4mt x 32ks x 32lane x 4 = 16384 floats
#define HP_F    16384       // Hperm: 4mt x 4ks x 32lane x 4 = 2048 floats
#define B1_F    18432       // 1024
#define B2_F    19456       // 256
#define TOK_F   19712       // 64 ints
#define GATE_F  19776       // 64
#define SMEM_FLOATS 19840
#define SMEM_BYTES  (SMEM_FLOATS * 4)    // 79360

// ---------------- device scratch ----------------
__device__ int   g_cnt [NVIEW * NE];
__device__ int   g_tok [NVIEW * NE * N_TOK];
__device__ float g_gate[NVIEW * NE * N_TOK];
__device__ float g_w1p [NE * DM * HID];   // W1, tf32-rounded, B-frag order
__device__ float g_w2p [NE * HID * DM];   // W2, tf32-rounded, B-frag order

// ---------------- helpers ----------------
__device__ __forceinline__ float tf32r(float x) {
    asm("cvt.rna.tf32.f32 %0, %1;" : "=f"(x) : "f"(x));
    return x;
}
__device__ __forceinline__ float4 tf32r4(float4 v) {
    v.x = tf32r(v.x); v.y = tf32r(v.y); v.z = tf32r(v.z); v.w = tf32r(v.w);
    return v;
}
__device__ __forceinline__ float d4(float4 a, float4 b) {
    return a.x * b.x + a.y * b.y + a.z * b.z + a.w * b.w;
}
__device__ __forceinline__ float wredsum(float x) {
#pragma unroll
    for (int o = 16; o > 0; o >>= 1) x += __shfl_xor_sync(0xffffffffu, x, o);
    return x;
}
__device__ __forceinline__ float gelu_exact(float x) {
    return 0.5f * x * (1.0f + erff(x * 0.70710678118654752440f));
}
// m16n8k8 tf32 mma: D += A*B, A 4 regs, B 2 regs, D 4 fp32
__device__ __forceinline__ void mma8(float4& d, const uint4& a,
                                     uint32_t b0, uint32_t b1) {
    asm volatile(
        "mma.sync.aligned.m16n8k8.row.col.f32.tf32.tf32.f32 "
        "{%0,%1,%2,%3}, {%4,%5,%6,%7}, {%8,%9}, {%0,%1,%2,%3};"
        : "+f"(d.x), "+f"(d.y), "+f"(d.z), "+f"(d.w)
        : "r"(a.x), "r"(a.y), "r"(a.z), "r"(a.w), "r"(b0), "r"(b1));
}

// ---------------- kernel 0: prep ----------------
// Rounds weights to tf32-rna and permutes into B-fragment order.
// f4 layout per (e, chunk jc): W1: [nt(4)][kp(16)][lane(32)] ; W2: [nt(32)][kp(2)][lane(32)]
// f4 components = (b0 s=2kp, b1 s=2kp, b0 s=2kp+1, b1 s=2kp+1);
//   b0: k = 8s + (lane&3), b1: k = 8s + (lane&3) + 4 ; n = nt*8 + (lane>>2)
__global__ void prep_kernel(const float* __restrict__ W1,
                            const float* __restrict__ W2) {
    __shared__ float s[256 * 36];
    int tid = threadIdx.x, b = blockIdx.x;
    if (b == 0 && tid < NVIEW * NE) g_cnt[tid] = 0;
    if (b < 512) {
        int e = b >> 5, jc = b & 31;
        for (int i = tid; i < 2048; i += 256) {
            int d = i >> 3, j4 = i & 7;
            float4 v = ((const float4*)(W1 + ((size_t)e * DM + d) * HID + jc * 32))[j4];
            *(float4*)&s[d * 36 + j4 * 4] = tf32r4(v);
        }
        __syncthreads();
        float4* dst = (float4*)g_w1p + (size_t)(e * 32 + jc) * 2048;
        for (int o = tid; o < 2048; o += 256) {
            int nt = o >> 9, kp = (o >> 5) & 15, ln = o & 31;
            int tig = ln & 3, g = ln >> 2;
            int jl = nt * 8 + g;
            float4 v;
            v.x = s[(16 * kp + tig) * 36 + jl];
            v.y = s[(16 * kp + tig + 4) * 36 + jl];
            v.z = s[(16 * kp + 8 + tig) * 36 + jl];
            v.w = s[(16 * kp + 8 + tig + 4) * 36 + jl];
            dst[o] = v;
        }
    } else {
        int e = (b - 512) >> 5, jc = (b - 512) & 31;
        for (int i = tid; i < 2048; i += 256) {
            int rl = i >> 6, n4 = i & 63;
            float4 v = ((const float4*)(W2 + ((size_t)e * HID + jc * 32 + rl) * DM))[n4];
            *(float4*)&s[rl * 260 + n4 * 4] = tf32r4(v);
        }
        __syncthreads();
        float4* dst = (float4*)g_w2p + (size_t)(e * 32 + jc) * 2048;
        for (int o = tid; o < 2048; o += 256) {
            int nt = o >> 6, kp = (o >> 5) & 1, ln = o & 31;
            int tig = ln & 3, g = ln >> 2;
            int n = nt * 8 + g;
            float4 v;
            v.x = s[(16 * kp + tig) * 260 + n];
            v.y = s[(16 * kp + tig + 4) * 260 + n];
            v.z = s[(16 * kp + 8 + tig) * 260 + n];
            v.w = s[(16 * kp + 8 + tig + 4) * 260 + n];
            dst[o] = v;
        }
    }
}

// ---------------- kernel 1: router (bit-exact fp32 sequence, from R3) --------
__global__ void router_kernel(const float* __restrict__ v0,
                              const float* __restrict__ v1,
                              const float* __restrict__ v2,
                              const float* __restrict__ rw,
                              const float* __restrict__ keys) {
    int vi   = blockIdx.y;
    int warp = threadIdx.x >> 5;
    int lane = threadIdx.x & 31;
    int tok  = blockIdx.x * 8 + warp;
    if (tok >= N_TOK) return;

    const float* vbase = (vi == 0) ? v0 : ((vi == 1) ? v1 : v2);
    const float* v = vbase + tok * DM;

    float4 a = ((const float4*)v)[lane];
    float4 b = ((const float4*)v)[lane + 32];

    float vv = wredsum(d4(a, a) + d4(b, b));

    const float* rwv = rw + (size_t)vi * NE * DM;
    float lg[NE];
#pragma unroll
    for (int e = 0; e < NE; e++) {
        const float4* kp = (const float4*)(keys + e * DM);
        const float4* rp = (const float4*)(rwv + e * DM);
        float4 k1 = kp[lane], k2 = kp[lane + 32];
        float4 r1 = rp[lane], r2 = rp[lane + 32];
        float dk = wredsum(d4(a, k1) + d4(b, k2));
        float dr = wredsum(d4(a, r1) + d4(b, r2));
        float kk = wredsum(d4(k1, k1) + d4(k2, k2));
        float sq = (vv + kk) - 2.0f * dk;
        lg[e] = (-sq) + dr;
    }

    if (lane == 0) {
        unsigned chosen = 0;
        float tv[TOPK];
        int   ti[TOPK];
#pragma unroll
        for (int k = 0; k < TOPK; k++) {
            float m = -1e30f; int mi = 0;
#pragma unroll
            for (int e = 0; e < NE; e++) {
                if (!((chosen >> e) & 1u) && lg[e] > m) { m = lg[e]; mi = e; }
            }
            tv[k] = m; ti[k] = mi; chosen |= (1u << mi);
        }
        float s = 0.f;
        float ex[TOPK];
#pragma unroll
        for (int k = 0; k < TOPK; k++) { ex[k] = expf(tv[k] - tv[0]); s += ex[k]; }
        float inv = 1.0f / s;
#pragma unroll
        for (int k = 0; k < TOPK; k++) {
            int ge  = vi * NE + ti[k];
            int pos = atomicAdd(&g_cnt[ge], 1);
            g_tok [ge * N_TOK + pos] = tok;
            g_gate[ge * N_TOK + pos] = ex[k] * inv;
        }
    }
}

// ---------------- kernel 2: grouped FFN on mma.sync tf32 ----------------
extern "C" __global__ void __launch_bounds__(256, 2)
ffn_kernel(const float* __restrict__ v0, const float* __restrict__ v1,
           const float* __restrict__ v2,
           const float* __restrict__ b1, const float* __restrict__ b2,
           float* __restrict__ out) {
    extern __shared__ float sm[];
    int tid = threadIdx.x, wid = tid >> 5, lane = tid & 31;
    int vi = blockIdx.z, e = blockIdx.y, g0 = vi * NE + e;
    int cnt = g_cnt[g0];
    int t0 = blockIdx.x * TM;
    if (t0 >= cnt) return;
    int rows = min(TM, cnt - t0);

    int*   s_tok  = (int*)&sm[TOK_F];
    float* s_gate = &sm[GATE_F];
    if (tid < TM) {
        int idx = t0 + tid;
        s_tok [tid] = (idx < cnt) ? g_tok [g0 * N_TOK + idx] : 0;
        s_gate[tid] = (idx < cnt) ? g_gate[g0 * N_TOK + idx] : 0.0f;
    }
    for (int i = tid; i < HID; i += 256) sm[B1_F + i] = b1[(size_t)e * HID + i];
    for (int i = tid; i < DM;  i += 256) sm[B2_F + i] = b2[(size_t)e * DM + i];
    __syncthreads();

    const float* V = (vi == 0) ? v0 : ((vi == 1) ? v1 : v2);

    // ---- gather X -> A-fragment-permuted smem (tf32-rna) ----
    for (int i = tid; i < TM * 64; i += 256) {
        int r = i >> 6, c4 = i & 63;
        float4 v = make_float4(0.f, 0.f, 0.f, 0.f);
        if (r < rows) v = tf32r4(((const float4*)(V + (size_t)s_tok[r] * DM))[c4]);
        int mt = r >> 4, pair = (r >> 3) & 1, gg = r & 7;
        int ks = c4 >> 1, q = pair + 2 * (c4 & 1);
        int base = ((mt * 32 + ks) * 32 + gg * 4) * 4 + q;
        sm[XP_F + base     ] = v.x;
        sm[XP_F + base + 4 ] = v.y;
        sm[XP_F + base + 8 ] = v.z;
        sm[XP_F + base + 12] = v.w;
    }
    __syncthreads();

    const uint4* XP  = (const uint4*)&sm[XP_F];
    const uint4* HPl = (const uint4*)&sm[HP_F];
    float*       HPs = &sm[HP_F];
    const uint4* W1P = (const uint4*)g_w1p + (size_t)(e * 32) * 2048;
    const uint4* W2P = (const uint4*)g_w2p + (size_t)(e * 32) * 2048;

    const int mt1 = wid >> 1, ntb = (wid & 1) * 2;   // GEMM1: tile (mt1, ntb/ntb+1)
    const int p2  = wid >> 2, o2  = wid & 3;         // GEMM2: m-pair p2, n-octet o2
    const int gg  = lane >> 2, cc = lane & 3;

    float4 acc[2][8];
#pragma unroll
    for (int i = 0; i < 2; i++)
#pragma unroll
        for (int j = 0; j < 8; j++) acc[i][j] = make_float4(0.f, 0.f, 0.f, 0.f);

#pragma unroll 1
    for (int jc = 0; jc < 32; jc++) {
        // ---- GEMM1: H-tiles (mt1, ntb), (mt1, ntb+1), K = 256 ----
        float4 a0 = make_float4(0.f, 0.f, 0.f, 0.f);
        float4 a1 = make_float4(0.f, 0.f, 0.f, 0.f);
        const uint4* xb  = XP  + mt1 * 1024 + lane;
        const uint4* w1b = W1P + jc * 2048 + ntb * 512 + lane;
#pragma unroll
        for (int kp = 0; kp < 16; kp++) {
            uint4 alo = xb[(2 * kp) * 32];
            uint4 ahi = xb[(2 * kp + 1) * 32];
            uint4 bA  = w1b[kp * 32];
            uint4 bB  = w1b[512 + kp * 32];
            mma8(a0, alo, bA.x, bA.y);
            mma8(a0, ahi, bA.z, bA.w);
            mma8(a1, alo, bB.x, bB.y);
            mma8(a1, ahi, bB.z, bB.w);
        }
        __syncthreads();   // previous GEMM2 finished reading Hperm

        // ---- bias + exact GELU -> Hperm (tf32-rna), A-frag order ----
        {
            int qb = 2 * (cc >> 1);
            int l0 = gg * 4 + ((2 * cc) & 3);
            int l1 = gg * 4 + ((2 * cc + 1) & 3);
#pragma unroll
            for (int t = 0; t < 2; t++) {
                int nt = ntb + t;
                float4 av = t ? a1 : a0;
                int jl = nt * 8 + 2 * cc;
                float bx = sm[B1_F + jc * 32 + jl];
                float by = sm[B1_F + jc * 32 + jl + 1];
                int fb = (mt1 * 4 + nt) * 32;
                HPs[(fb + l0) * 4 + qb    ] = tf32r(gelu_exact(av.x + bx));
                HPs[(fb + l1) * 4 + qb    ] = tf32r(gelu_exact(av.y + by));
                HPs[(fb + l0) * 4 + qb + 1] = tf32r(gelu_exact(av.z + bx));
                HPs[(fb + l1) * 4 + qb + 1] = tf32r(gelu_exact(av.w + by));
            }
        }
        __syncthreads();   // Hperm visible

        // ---- GEMM2: acc += H[64,32] @ W2c[32,256] ----
        const uint4* w2b = W2P + jc * 2048 + o2 * 512 + lane;
#pragma unroll
        for (int kp = 0; kp < 2; kp++) {
            uint4 h00 = HPl[((2 * p2) * 4 + 2 * kp) * 32 + lane];
            uint4 h01 = HPl[((2 * p2) * 4 + 2 * kp + 1) * 32 + lane];
            uint4 h10 = HPl[((2 * p2 + 1) * 4 + 2 * kp) * 32 + lane];
            uint4 h11 = HPl[((2 * p2 + 1) * 4 + 2 * kp + 1) * 32 + lane];
#pragma unroll
            for (int nt = 0; nt < 8; nt++) {
                uint4 bb = w2b[(nt * 2 + kp) * 32];
                mma8(acc[0][nt], h00, bb.x, bb.y);
                mma8(acc[0][nt], h01, bb.z, bb.w);
                mma8(acc[1][nt], h10, bb.x, bb.y);
                mma8(acc[1][nt], h11, bb.z, bb.w);
            }
        }
    }

    // ---- epilogue: out[tok,:] += gate * (acc + b2) ----
#pragma unroll
    for (int nt = 0; nt < 8; nt++) {
        int col = (o2 * 8 + nt) * 8 + 2 * cc;
        float b2a = sm[B2_F + col], b2b = sm[B2_F + col + 1];
#pragma unroll
        for (int mi = 0; mi < 2; mi++) {
            float4 f = acc[mi][nt];
            int ra = (2 * p2 + mi) * 16 + gg;
            int rb = ra + 8;
            if (ra < rows) {
                float gt = s_gate[ra];
                float* ob = out + (size_t)s_tok[ra] * DM;
                atomicAdd(ob + col,     gt * (f.x + b2a));
                atomicAdd(ob + col + 1, gt * (f.y + b2b));
            }
            if (rb < rows) {
                float gt = s_gate[rb];
                float* ob = out + (size_t)s_tok[rb] * DM;
                atomicAdd(ob + col,     gt * (f.z + b2a));
                atomicAdd(ob + col + 1, gt * (f.w + b2b));
            }
        }
    }
}

// ---------------- launch ----------------
extern "C" void kernel_launch(void* const* d_in, const int* in_sizes, int n_in,
                              void* d_out, int out_size) {
    const float* v0   = (const float*)d_in[0];
    const float* v1   = (const float*)d_in[1];
    const float* v2   = (const float*)d_in[2];
    const float* rw   = (const float*)d_in[3];
    const float* keys = (const float*)d_in[4];
    const float* W1   = (const float*)d_in[5];
    const float* b1   = (const float*)d_in[6];
    const float* W2   = (const float*)d_in[7];
    const float* b2   = (const float*)d_in[8];
    float* out = (float*)d_out;

    cudaFuncSetAttribute(ffn_kernel, cudaFuncAttributeMaxDynamicSharedMemorySize,
                         SMEM_BYTES);

    cudaMemsetAsync(d_out, 0, (size_t)out_size * sizeof(float), 0);

    prep_kernel<<<1024, 256, 0, 0>>>(W1, W2);

    dim3 rgrid(N_TOK / 8, NVIEW, 1);
    router_kernel<<<rgrid, 256, 0, 0>>>(v0, v1, v2, rw, keys);

    dim3 fgrid(N_TOK / TM, NE, NVIEW);   // 128 x 16 x 3, most blocks exit early
    ffn_kernel<<<fgrid, 256, SMEM_BYTES, 0>>>(v0, v1, v2, b1, b2, out);
}